// round 11
// baseline (speedup 1.0000x reference)
#include <cuda_runtime.h>
#include <cuda_fp16.h>
#include <cstdint>
#include <cstddef>

// ===========================================================================
// MinGRU B=4 S=4096 D=1024. Round 11:
//  - fp16 mma.sync triple GEMM (legacy-HMMA rate floor) + fused chunk stats
//  - xs/a interleaved in one uint2 array (8B store/load per 2-channel pair)
//  - carry fused into final_scan (warp-uniform prefix loop over P/L)
//  - single conversion kernel (3 launches total)
// ===========================================================================

#define Bdim 4
#define Sdim 4096
#define Ddim 1024
#define Mdim (Bdim * Sdim)        // 16384

#define NCHUNK 32
#define CHUNK  128
#define NCH    (Bdim * Ddim)      // 4096

// g_xa[p] = { xs_half2, a_half2 } for channel pair p
__device__ uint2  g_xa [(size_t)Mdim * Ddim / 2];   // 64 MB
__device__ __half g_xh [(size_t)Mdim * Ddim];       // 32 MB (fp16 x)
__device__ __half g_wh [(size_t)3 * Ddim * Ddim];   //  6 MB (fp16 W)
__device__ float  g_P  [NCHUNK * NCH];
__device__ float  g_L  [NCHUNK * NCH];

// ---------------------------------------------------------------------------
__device__ __forceinline__ uint32_t smem_u32(const void* p) {
    uint32_t a;
    asm("{ .reg .u64 t; cvta.to.shared.u64 t, %1; cvt.u32.u64 %0, t; }"
        : "=r"(a) : "l"(p));
    return a;
}

__device__ __forceinline__ void cp_async16(uint32_t dst, const void* src) {
    asm volatile("cp.async.cg.shared.global [%0], [%1], 16;"
                 :: "r"(dst), "l"(src) : "memory");
}
#define CP_COMMIT() asm volatile("cp.async.commit_group;" ::: "memory")
#define CP_WAIT1()  asm volatile("cp.async.wait_group 1;"  ::: "memory")

__device__ __forceinline__ void ldsm_x4(uint32_t* r, uint32_t addr) {
    asm volatile("ldmatrix.sync.aligned.m8n8.x4.shared.b16 {%0,%1,%2,%3}, [%4];"
                 : "=r"(r[0]), "=r"(r[1]), "=r"(r[2]), "=r"(r[3]) : "r"(addr));
}

__device__ __forceinline__ void mma_fp16(float* c, const uint32_t* a,
                                         uint32_t b0, uint32_t b1) {
    asm volatile(
        "mma.sync.aligned.m16n8k16.row.col.f32.f16.f16.f32 "
        "{%0,%1,%2,%3}, {%4,%5,%6,%7}, {%8,%9}, {%0,%1,%2,%3};"
        : "+f"(c[0]), "+f"(c[1]), "+f"(c[2]), "+f"(c[3])
        : "r"(a[0]), "r"(a[1]), "r"(a[2]), "r"(a[3]), "r"(b0), "r"(b1));
}

__device__ __forceinline__ float sigmoidf_(float z) { return 1.0f / (1.0f + __expf(-z)); }
__device__ __forceinline__ float tanhf_(float z)    { return 2.0f / (1.0f + __expf(-2.0f * z)) - 1.0f; }

// ---------------------------------------------------------------------------
// Kernel 0: ALL fp32 -> fp16 conversions (x, Wg, Wv, Wd) in one launch
// ---------------------------------------------------------------------------
#define NX4 (Mdim * Ddim / 4)     // 4,194,304
#define NW4 (Ddim * Ddim / 4)     //   262,144

__global__ void convert_all_kernel(const float4* __restrict__ x,
                                   const float4* __restrict__ w0,
                                   const float4* __restrict__ w1,
                                   const float4* __restrict__ w2,
                                   uint2* __restrict__ xh,
                                   uint2* __restrict__ wh)
{
    const int i = blockIdx.x * blockDim.x + threadIdx.x;  // 0 .. NX4+3*NW4-1
    const float4* src;
    uint2* dst;
    int j;
    if (i < NX4) {
        src = x;  dst = xh;  j = i;
    } else {
        const int k   = i - NX4;
        const int mat = k / NW4;
        j   = k - mat * NW4;
        src = (mat == 0) ? w0 : (mat == 1) ? w1 : w2;
        dst = wh + (size_t)mat * NW4;
    }
    float4 v = src[j];
    __half2 lo = __floats2half2_rn(v.x, v.y);
    __half2 hi = __floats2half2_rn(v.z, v.w);
    uint2 o;
    o.x = *reinterpret_cast<uint32_t*>(&lo);
    o.y = *reinterpret_cast<uint32_t*>(&hi);
    dst[j] = o;
}

// ---------------------------------------------------------------------------
// Kernel 1: fused triple GEMM + activations + per-chunk scan stats
//  BM=128 (== one scan chunk), BN=64, BK=32, 3-stage cp.async, 2 CTAs/SM.
// ---------------------------------------------------------------------------
#define BK 32
#define NSTAGE 3
#define ASTRB 80
#define A_SM_BYTES (128 * ASTRB)                    // 10240
#define B_SM_BYTES (64 * ASTRB)                     // 5120
#define STAGE_BYTES (A_SM_BYTES + 3 * B_SM_BYTES)   // 25600
#define GEMM_SMEM (NSTAGE * STAGE_BYTES)            // 76800
#define EPI_STR 66

extern __shared__ char gemm_smem[];

__device__ __forceinline__ void issue_stage(const __half* __restrict__ xh,
                                            const __half* __restrict__ wh,
                                            int m0, int n0, int k0,
                                            uint32_t smbase, int s, int tid)
{
    const uint32_t stg = smbase + (uint32_t)s * STAGE_BYTES;
    #pragma unroll
    for (int t = 0; t < 2; t++) {
        const int c   = tid + t * 256;
        const int row = c >> 2, kc = c & 3;
        cp_async16(stg + row * ASTRB + kc * 16,
                   xh + (size_t)(m0 + row) * Ddim + k0 + kc * 8);
    }
    #pragma unroll
    for (int t = 0; t < 3; t++) {
        const int c   = tid + t * 256;
        const int mat = c >> 8;
        const int cc  = c & 255;
        const int row = cc >> 2, kc = cc & 3;
        cp_async16(stg + A_SM_BYTES + mat * B_SM_BYTES + row * ASTRB + kc * 16,
                   wh + (size_t)mat * (Ddim * Ddim) +
                        (size_t)(n0 + row) * Ddim + k0 + kc * 8);
    }
}

__global__ __launch_bounds__(256, 2)
void gemm3_fp16_kernel(const __half* __restrict__ xh,
                       const __half* __restrict__ wh,
                       const float* __restrict__ bg,
                       const float* __restrict__ bv,
                       const float* __restrict__ bd)
{
    const int tid  = threadIdx.x;
    const int lane = tid & 31;
    const int wid  = tid >> 5;
    const int m0   = blockIdx.x * 128;
    const int n0   = blockIdx.y * 64;
    const int wm   = (wid & 3) * 32;
    const int wn   = (wid >> 2) * 32;
    const int grp  = lane >> 2;
    const int tg   = lane & 3;

    const uint32_t smbase = smem_u32(gemm_smem);

    const uint32_t a_lane_off =
        (uint32_t)((lane & 15) * ASTRB + (lane >> 4) * 16);
    const uint32_t b_lane_off =
        (uint32_t)(((lane >> 4) * 8 + (lane & 7)) * ASTRB + ((lane >> 3) & 1) * 16);

    float acc[3][2][4][4];
    #pragma unroll
    for (int w = 0; w < 3; w++)
        #pragma unroll
        for (int mi = 0; mi < 2; mi++)
            #pragma unroll
            for (int ni = 0; ni < 4; ni++)
                #pragma unroll
                for (int r = 0; r < 4; r++) acc[w][mi][ni][r] = 0.0f;

    #pragma unroll
    for (int s = 0; s < NSTAGE - 1; s++) {
        issue_stage(xh, wh, m0, n0, s * BK, smbase, s, tid);
        CP_COMMIT();
    }

    const int NITER = Ddim / BK;   // 32
    int slot = 0;
    for (int it = 0; it < NITER; it++) {
        CP_WAIT1();
        __syncthreads();

        const int ns = it + NSTAGE - 1;
        if (ns < NITER) {
            int nslot = slot + (NSTAGE - 1);
            if (nslot >= NSTAGE) nslot -= NSTAGE;
            issue_stage(xh, wh, m0, n0, ns * BK, smbase, nslot, tid);
        }
        CP_COMMIT();

        const uint32_t stg = smbase + (uint32_t)slot * STAGE_BYTES;
        #pragma unroll
        for (int ks = 0; ks < 2; ks++) {
            uint32_t afrag[2][4];
            #pragma unroll
            for (int mi = 0; mi < 2; mi++)
                ldsm_x4(afrag[mi],
                        stg + (wm + mi * 16) * ASTRB + ks * 32 + a_lane_off);
            #pragma unroll
            for (int mat = 0; mat < 3; mat++) {
                #pragma unroll
                for (int np = 0; np < 2; np++) {
                    uint32_t bfrag[4];
                    ldsm_x4(bfrag,
                            stg + A_SM_BYTES + mat * B_SM_BYTES +
                            (wn + np * 16) * ASTRB + ks * 32 + b_lane_off);
                    #pragma unroll
                    for (int h = 0; h < 2; h++) {
                        mma_fp16(acc[mat][0][np * 2 + h], afrag[0],
                                 bfrag[h * 2], bfrag[h * 2 + 1]);
                        mma_fp16(acc[mat][1][np * 2 + h], afrag[1],
                                 bfrag[h * 2], bfrag[h * 2 + 1]);
                    }
                }
            }
        }
        __syncthreads();
        if (++slot == NSTAGE) slot = 0;
    }

    // ---- epilogue: bias+activations -> interleaved g_xa + smem stage
    float* xs_sm = (float*)gemm_smem;                 // [128][EPI_STR]
    float* a_sm  = xs_sm + 128 * EPI_STR;             // [128][EPI_STR]

    #pragma unroll
    for (int mi = 0; mi < 2; mi++) {
        const int rl = wm + mi * 16 + grp;
        #pragma unroll
        for (int ni = 0; ni < 4; ni++) {
            const int cl = wn + ni * 8 + tg * 2;
            const int cc = n0 + cl;
            const float bg0 = bg[cc], bg1 = bg[cc + 1];
            const float bv0 = bv[cc], bv1 = bv[cc + 1];
            const float bd0 = bd[cc], bd1 = bd[cc + 1];
            #pragma unroll
            for (int rr = 0; rr < 2; rr++) {
                const int rloc = rl + rr * 8;
                const int row  = m0 + rloc;
                const float gg0 = acc[0][mi][ni][rr * 2 + 0] + bg0;
                const float gg1 = acc[0][mi][ni][rr * 2 + 1] + bg1;
                const float vv0 = acc[1][mi][ni][rr * 2 + 0] + bv0;
                const float vv1 = acc[1][mi][ni][rr * 2 + 1] + bv1;
                const float dd0 = acc[2][mi][ni][rr * 2 + 0] + bd0;
                const float dd1 = acc[2][mi][ni][rr * 2 + 1] + bd1;

                const float xs0 = sigmoidf_(gg0) * tanhf_(vv0);
                const float xs1 = sigmoidf_(gg1) * tanhf_(vv1);
                const float aa0 = 0.001f + 0.998f * sigmoidf_(dd0);
                const float aa1 = 0.001f + 0.998f * sigmoidf_(dd1);

                __half2 xsh2 = __floats2half2_rn(xs0, xs1);
                __half2 aah2 = __floats2half2_rn(aa0, aa1);
                uint2 pkt;
                pkt.x = *reinterpret_cast<uint32_t*>(&xsh2);
                pkt.y = *reinterpret_cast<uint32_t*>(&aah2);
                const size_t off = (size_t)row * Ddim + cc;
                g_xa[off >> 1] = pkt;

                // stage the ROUNDED values so P/L match final_scan exactly
                const float2 xsr = __half22float2(xsh2);
                const float2 aar = __half22float2(aah2);
                xs_sm[rloc * EPI_STR + cl]     = xsr.x;
                xs_sm[rloc * EPI_STR + cl + 1] = xsr.y;
                a_sm [rloc * EPI_STR + cl]     = aar.x;
                a_sm [rloc * EPI_STR + cl + 1] = aar.y;
            }
        }
    }
    __syncthreads();

    // ---- fused chunk stats
    if (tid < 64) {
        float P = 1.0f, L = 0.0f;
        #pragma unroll 8
        for (int t = 0; t < CHUNK; t++) {
            const float a  = a_sm [t * EPI_STR + tid];
            const float xv = xs_sm[t * EPI_STR + tid];
            L = fmaf(a, L, xv);
            P *= a;
        }
        const int b     = blockIdx.x >> 5;
        const int chunk = blockIdx.x & 31;
        const int gi    = chunk * NCH + b * Ddim + n0 + tid;
        g_P[gi] = P;
        g_L[gi] = L;
    }
}

// ---------------------------------------------------------------------------
// Kernel 2: final scan, 2 channels/thread; carry-in computed in-thread from
// P/L (warp-uniform prefix loop — chunk is constant across each CTA).
// ---------------------------------------------------------------------------
__global__ void final_scan_kernel(float* __restrict__ out)
{
    const int t = blockIdx.x * blockDim.x + threadIdx.x;   // 0..65535
    const int ch2   = t & (NCH / 2 - 1);                   // channel pair id
    const int chunk = t >> 11;                             // uniform per CTA
    const int b  = ch2 >> 9;
    const int d2 = ch2 & 511;
    const int cibase = b * Ddim + d2 * 2;                  // channel base in NCH

    // carry-in: identical fmaf chain to the old carry_kernel
    float h0 = 0.0f, h1 = 0.0f;
    #pragma unroll 8
    for (int c = 0; c < chunk; c++) {
        const float2 P = *(const float2*)(g_P + c * NCH + cibase);
        const float2 L = *(const float2*)(g_L + c * NCH + cibase);
        h0 = fmaf(P.x, h0, L.x);
        h1 = fmaf(P.y, h1, L.y);
    }

    const size_t base = ((size_t)b * Sdim + (size_t)chunk * CHUNK) * Ddim + d2 * 2;
    #pragma unroll 4
    for (int i = 0; i < CHUNK; i++) {
        const size_t off = base + (size_t)i * Ddim;
        const uint2 pkt = g_xa[off >> 1];
        const __half2 xsh2 = *reinterpret_cast<const __half2*>(&pkt.x);
        const __half2 aah2 = *reinterpret_cast<const __half2*>(&pkt.y);
        const float2 xv = __half22float2(xsh2);
        const float2 a  = __half22float2(aah2);
        h0 = fmaf(a.x, h0, xv.x);
        h1 = fmaf(a.y, h1, xv.y);
        *(float2*)(out + off) = make_float2(h0, h1);
    }
}

// ---------------------------------------------------------------------------
// Host
// ---------------------------------------------------------------------------
extern "C" void kernel_launch(void* const* d_in, const int* in_sizes, int n_in,
                              void* d_out, int out_size)
{
    const float* x  = (const float*)d_in[0];
    const float* Wg = (const float*)d_in[1];
    const float* bg = (const float*)d_in[2];
    const float* Wv = (const float*)d_in[3];
    const float* bv = (const float*)d_in[4];
    const float* Wd = (const float*)d_in[5];
    const float* bd = (const float*)d_in[6];
    float* out = (float*)d_out;

    void *p_xh, *p_wh;
    cudaGetSymbolAddress(&p_xh, g_xh);
    cudaGetSymbolAddress(&p_wh, g_wh);

    static bool attr_set = false;
    if (!attr_set) {
        cudaFuncSetAttribute(gemm3_fp16_kernel,
                             cudaFuncAttributeMaxDynamicSharedMemorySize, GEMM_SMEM);
        attr_set = true;
    }

    // 0: all conversions in one launch (NX4 + 3*NW4 = 4,980,736 threads)
    convert_all_kernel<<<(NX4 + 3 * NW4) / 256, 256>>>(
        (const float4*)x, (const float4*)Wg, (const float4*)Wv, (const float4*)Wd,
        (uint2*)p_xh, (uint2*)p_wh);

    // 1: fused triple GEMM + activations + chunk stats
    dim3 g1(Mdim / 128, Ddim / 64);      // (128, 16)
    gemm3_fp16_kernel<<<g1, 256, GEMM_SMEM>>>((const __half*)p_xh, (const __half*)p_wh,
                                              bg, bv, bd);

    // 2: final scan (carry fused)
    final_scan_kernel<<<(NCHUNK * NCH / 2) / 256, 256>>>(out);
}

// round 13
// speedup vs baseline: 1.0443x; 1.0443x over previous
#include <cuda_runtime.h>
#include <cuda_fp16.h>
#include <cstdint>
#include <cstddef>

// ===========================================================================
// MinGRU B=4 S=4096 D=1024. Round 12:
//  - fp16 mma.sync triple GEMM (legacy-HMMA rate floor) + fused chunk stats
//  - CHUNK=64 (NCHUNK=64): 2x scan parallelism (final_scan was latency-bound)
//  - separate carry kernel with batched prefetch (R10 pattern, 4x16)
//  - xs/a interleaved uint2; single conversion kernel
// ===========================================================================

#define Bdim 4
#define Sdim 4096
#define Ddim 1024
#define Mdim (Bdim * Sdim)        // 16384

#define NCHUNK 64
#define CHUNK  64                 // NCHUNK*CHUNK == Sdim
#define NCH    (Bdim * Ddim)      // 4096

// g_xa[p] = { xs_half2, a_half2 } for channel pair p
__device__ uint2  g_xa [(size_t)Mdim * Ddim / 2];   // 64 MB
__device__ __half g_xh [(size_t)Mdim * Ddim];       // 32 MB (fp16 x)
__device__ __half g_wh [(size_t)3 * Ddim * Ddim];   //  6 MB (fp16 W)
__device__ float  g_P  [NCHUNK * NCH];              // 1 MB
__device__ float  g_L  [NCHUNK * NCH];              // 1 MB
__device__ float  g_cin[NCHUNK * NCH];              // 1 MB

// ---------------------------------------------------------------------------
__device__ __forceinline__ uint32_t smem_u32(const void* p) {
    uint32_t a;
    asm("{ .reg .u64 t; cvta.to.shared.u64 t, %1; cvt.u32.u64 %0, t; }"
        : "=r"(a) : "l"(p));
    return a;
}

__device__ __forceinline__ void cp_async16(uint32_t dst, const void* src) {
    asm volatile("cp.async.cg.shared.global [%0], [%1], 16;"
                 :: "r"(dst), "l"(src) : "memory");
}
#define CP_COMMIT() asm volatile("cp.async.commit_group;" ::: "memory")
#define CP_WAIT1()  asm volatile("cp.async.wait_group 1;"  ::: "memory")

__device__ __forceinline__ void ldsm_x4(uint32_t* r, uint32_t addr) {
    asm volatile("ldmatrix.sync.aligned.m8n8.x4.shared.b16 {%0,%1,%2,%3}, [%4];"
                 : "=r"(r[0]), "=r"(r[1]), "=r"(r[2]), "=r"(r[3]) : "r"(addr));
}

__device__ __forceinline__ void mma_fp16(float* c, const uint32_t* a,
                                         uint32_t b0, uint32_t b1) {
    asm volatile(
        "mma.sync.aligned.m16n8k16.row.col.f32.f16.f16.f32 "
        "{%0,%1,%2,%3}, {%4,%5,%6,%7}, {%8,%9}, {%0,%1,%2,%3};"
        : "+f"(c[0]), "+f"(c[1]), "+f"(c[2]), "+f"(c[3])
        : "r"(a[0]), "r"(a[1]), "r"(a[2]), "r"(a[3]), "r"(b0), "r"(b1));
}

__device__ __forceinline__ float sigmoidf_(float z) { return 1.0f / (1.0f + __expf(-z)); }
__device__ __forceinline__ float tanhf_(float z)    { return 2.0f / (1.0f + __expf(-2.0f * z)) - 1.0f; }

// ---------------------------------------------------------------------------
// Kernel 0: ALL fp32 -> fp16 conversions (x, Wg, Wv, Wd) in one launch
// ---------------------------------------------------------------------------
#define NX4 (Mdim * Ddim / 4)     // 4,194,304
#define NW4 (Ddim * Ddim / 4)     //   262,144

__global__ void convert_all_kernel(const float4* __restrict__ x,
                                   const float4* __restrict__ w0,
                                   const float4* __restrict__ w1,
                                   const float4* __restrict__ w2,
                                   uint2* __restrict__ xh,
                                   uint2* __restrict__ wh)
{
    const int i = blockIdx.x * blockDim.x + threadIdx.x;
    const float4* src;
    uint2* dst;
    int j;
    if (i < NX4) {
        src = x;  dst = xh;  j = i;
    } else {
        const int k   = i - NX4;
        const int mat = k / NW4;
        j   = k - mat * NW4;
        src = (mat == 0) ? w0 : (mat == 1) ? w1 : w2;
        dst = wh + (size_t)mat * NW4;
    }
    float4 v = src[j];
    __half2 lo = __floats2half2_rn(v.x, v.y);
    __half2 hi = __floats2half2_rn(v.z, v.w);
    uint2 o;
    o.x = *reinterpret_cast<uint32_t*>(&lo);
    o.y = *reinterpret_cast<uint32_t*>(&hi);
    dst[j] = o;
}

// ---------------------------------------------------------------------------
// Kernel 1: fused triple GEMM + activations + per-chunk scan stats
//  BM=128 rows == 2 scan chunks of 64; BN=64, BK=32, 3-stage, 2 CTAs/SM.
// ---------------------------------------------------------------------------
#define BK 32
#define NSTAGE 3
#define ASTRB 80
#define A_SM_BYTES (128 * ASTRB)                    // 10240
#define B_SM_BYTES (64 * ASTRB)                     // 5120
#define STAGE_BYTES (A_SM_BYTES + 3 * B_SM_BYTES)   // 25600
#define GEMM_SMEM (NSTAGE * STAGE_BYTES)            // 76800
#define EPI_STR 66

extern __shared__ char gemm_smem[];

__device__ __forceinline__ void issue_stage(const __half* __restrict__ xh,
                                            const __half* __restrict__ wh,
                                            int m0, int n0, int k0,
                                            uint32_t smbase, int s, int tid)
{
    const uint32_t stg = smbase + (uint32_t)s * STAGE_BYTES;
    #pragma unroll
    for (int t = 0; t < 2; t++) {
        const int c   = tid + t * 256;
        const int row = c >> 2, kc = c & 3;
        cp_async16(stg + row * ASTRB + kc * 16,
                   xh + (size_t)(m0 + row) * Ddim + k0 + kc * 8);
    }
    #pragma unroll
    for (int t = 0; t < 3; t++) {
        const int c   = tid + t * 256;
        const int mat = c >> 8;
        const int cc  = c & 255;
        const int row = cc >> 2, kc = cc & 3;
        cp_async16(stg + A_SM_BYTES + mat * B_SM_BYTES + row * ASTRB + kc * 16,
                   wh + (size_t)mat * (Ddim * Ddim) +
                        (size_t)(n0 + row) * Ddim + k0 + kc * 8);
    }
}

__global__ __launch_bounds__(256, 2)
void gemm3_fp16_kernel(const __half* __restrict__ xh,
                       const __half* __restrict__ wh,
                       const float* __restrict__ bg,
                       const float* __restrict__ bv,
                       const float* __restrict__ bd)
{
    const int tid  = threadIdx.x;
    const int lane = tid & 31;
    const int wid  = tid >> 5;
    const int m0   = blockIdx.x * 128;
    const int n0   = blockIdx.y * 64;
    const int wm   = (wid & 3) * 32;
    const int wn   = (wid >> 2) * 32;
    const int grp  = lane >> 2;
    const int tg   = lane & 3;

    const uint32_t smbase = smem_u32(gemm_smem);

    const uint32_t a_lane_off =
        (uint32_t)((lane & 15) * ASTRB + (lane >> 4) * 16);
    const uint32_t b_lane_off =
        (uint32_t)(((lane >> 4) * 8 + (lane & 7)) * ASTRB + ((lane >> 3) & 1) * 16);

    float acc[3][2][4][4];
    #pragma unroll
    for (int w = 0; w < 3; w++)
        #pragma unroll
        for (int mi = 0; mi < 2; mi++)
            #pragma unroll
            for (int ni = 0; ni < 4; ni++)
                #pragma unroll
                for (int r = 0; r < 4; r++) acc[w][mi][ni][r] = 0.0f;

    #pragma unroll
    for (int s = 0; s < NSTAGE - 1; s++) {
        issue_stage(xh, wh, m0, n0, s * BK, smbase, s, tid);
        CP_COMMIT();
    }

    const int NITER = Ddim / BK;   // 32
    int slot = 0;
    for (int it = 0; it < NITER; it++) {
        CP_WAIT1();
        __syncthreads();

        const int ns = it + NSTAGE - 1;
        if (ns < NITER) {
            int nslot = slot + (NSTAGE - 1);
            if (nslot >= NSTAGE) nslot -= NSTAGE;
            issue_stage(xh, wh, m0, n0, ns * BK, smbase, nslot, tid);
        }
        CP_COMMIT();

        const uint32_t stg = smbase + (uint32_t)slot * STAGE_BYTES;
        #pragma unroll
        for (int ks = 0; ks < 2; ks++) {
            uint32_t afrag[2][4];
            #pragma unroll
            for (int mi = 0; mi < 2; mi++)
                ldsm_x4(afrag[mi],
                        stg + (wm + mi * 16) * ASTRB + ks * 32 + a_lane_off);
            #pragma unroll
            for (int mat = 0; mat < 3; mat++) {
                #pragma unroll
                for (int np = 0; np < 2; np++) {
                    uint32_t bfrag[4];
                    ldsm_x4(bfrag,
                            stg + A_SM_BYTES + mat * B_SM_BYTES +
                            (wn + np * 16) * ASTRB + ks * 32 + b_lane_off);
                    #pragma unroll
                    for (int h = 0; h < 2; h++) {
                        mma_fp16(acc[mat][0][np * 2 + h], afrag[0],
                                 bfrag[h * 2], bfrag[h * 2 + 1]);
                        mma_fp16(acc[mat][1][np * 2 + h], afrag[1],
                                 bfrag[h * 2], bfrag[h * 2 + 1]);
                    }
                }
            }
        }
        __syncthreads();
        if (++slot == NSTAGE) slot = 0;
    }

    // ---- epilogue: bias+activations -> interleaved g_xa + smem stage
    float* xs_sm = (float*)gemm_smem;                 // [128][EPI_STR]
    float* a_sm  = xs_sm + 128 * EPI_STR;             // [128][EPI_STR]

    #pragma unroll
    for (int mi = 0; mi < 2; mi++) {
        const int rl = wm + mi * 16 + grp;
        #pragma unroll
        for (int ni = 0; ni < 4; ni++) {
            const int cl = wn + ni * 8 + tg * 2;
            const int cc = n0 + cl;
            const float bg0 = bg[cc], bg1 = bg[cc + 1];
            const float bv0 = bv[cc], bv1 = bv[cc + 1];
            const float bd0 = bd[cc], bd1 = bd[cc + 1];
            #pragma unroll
            for (int rr = 0; rr < 2; rr++) {
                const int rloc = rl + rr * 8;
                const int row  = m0 + rloc;
                const float gg0 = acc[0][mi][ni][rr * 2 + 0] + bg0;
                const float gg1 = acc[0][mi][ni][rr * 2 + 1] + bg1;
                const float vv0 = acc[1][mi][ni][rr * 2 + 0] + bv0;
                const float vv1 = acc[1][mi][ni][rr * 2 + 1] + bv1;
                const float dd0 = acc[2][mi][ni][rr * 2 + 0] + bd0;
                const float dd1 = acc[2][mi][ni][rr * 2 + 1] + bd1;

                const float xs0 = sigmoidf_(gg0) * tanhf_(vv0);
                const float xs1 = sigmoidf_(gg1) * tanhf_(vv1);
                const float aa0 = 0.001f + 0.998f * sigmoidf_(dd0);
                const float aa1 = 0.001f + 0.998f * sigmoidf_(dd1);

                __half2 xsh2 = __floats2half2_rn(xs0, xs1);
                __half2 aah2 = __floats2half2_rn(aa0, aa1);
                uint2 pkt;
                pkt.x = *reinterpret_cast<uint32_t*>(&xsh2);
                pkt.y = *reinterpret_cast<uint32_t*>(&aah2);
                const size_t off = (size_t)row * Ddim + cc;
                g_xa[off >> 1] = pkt;

                // stage the ROUNDED values so P/L match final_scan exactly
                const float2 xsr = __half22float2(xsh2);
                const float2 aar = __half22float2(aah2);
                xs_sm[rloc * EPI_STR + cl]     = xsr.x;
                xs_sm[rloc * EPI_STR + cl + 1] = xsr.y;
                a_sm [rloc * EPI_STR + cl]     = aar.x;
                a_sm [rloc * EPI_STR + cl + 1] = aar.y;
            }
        }
    }
    __syncthreads();

    // ---- fused chunk stats: BM tile = 2 chunks of 64; 128 threads active
    if (tid < 128) {
        const int ch   = tid & 63;            // channel within the 64-col tile
        const int half = tid >> 6;            // which 64-row chunk of the tile
        float P = 1.0f, L = 0.0f;
        #pragma unroll 8
        for (int t = 0; t < CHUNK; t++) {
            const int r = half * CHUNK + t;
            const float a  = a_sm [r * EPI_STR + ch];
            const float xv = xs_sm[r * EPI_STR + ch];
            L = fmaf(a, L, xv);
            P *= a;
        }
        const int b  = blockIdx.x >> 5;       // batch
        const int tb = blockIdx.x & 31;       // 128-row time block
        const int gi = (tb * 2 + half) * NCH + b * Ddim + n0 + ch;
        g_P[gi] = P;
        g_L[gi] = L;
    }
}

// ---------------------------------------------------------------------------
// Kernel 2: carry combine — batched prefetch (4 x 16), then register chain
// ---------------------------------------------------------------------------
__global__ void carry_kernel()
{
    const int ch = blockIdx.x * blockDim.x + threadIdx.x;  // 0..4095
    float h = 0.0f;
    #pragma unroll
    for (int base = 0; base < NCHUNK; base += 16) {
        float P[16], L[16];
        #pragma unroll
        for (int j = 0; j < 16; j++) {
            P[j] = g_P[(base + j) * NCH + ch];
            L[j] = g_L[(base + j) * NCH + ch];
        }
        #pragma unroll
        for (int j = 0; j < 16; j++) {
            g_cin[(base + j) * NCH + ch] = h;
            h = fmaf(P[j], h, L[j]);
        }
    }
}

// ---------------------------------------------------------------------------
// Kernel 3: final scan, 2 channels/thread, 64 steps (131072 threads)
// ---------------------------------------------------------------------------
__global__ void final_scan_kernel(float* __restrict__ out)
{
    const int t = blockIdx.x * blockDim.x + threadIdx.x;   // 0..131071
    const int ch2   = t & (NCH / 2 - 1);                   // channel pair id
    const int chunk = t >> 11;                             // 0..63
    const int b  = ch2 >> 9;
    const int d2 = ch2 & 511;

    const int ci = chunk * NCH + b * Ddim + d2 * 2;
    float h0 = g_cin[ci], h1 = g_cin[ci + 1];

    const size_t base = ((size_t)b * Sdim + (size_t)chunk * CHUNK) * Ddim + d2 * 2;
    #pragma unroll 4
    for (int i = 0; i < CHUNK; i++) {
        const size_t off = base + (size_t)i * Ddim;
        const uint2 pkt = g_xa[off >> 1];
        const __half2 xsh2 = *reinterpret_cast<const __half2*>(&pkt.x);
        const __half2 aah2 = *reinterpret_cast<const __half2*>(&pkt.y);
        const float2 xv = __half22float2(xsh2);
        const float2 a  = __half22float2(aah2);
        h0 = fmaf(a.x, h0, xv.x);
        h1 = fmaf(a.y, h1, xv.y);
        *(float2*)(out + off) = make_float2(h0, h1);
    }
}

// ---------------------------------------------------------------------------
// Host
// ---------------------------------------------------------------------------
extern "C" void kernel_launch(void* const* d_in, const int* in_sizes, int n_in,
                              void* d_out, int out_size)
{
    const float* x  = (const float*)d_in[0];
    const float* Wg = (const float*)d_in[1];
    const float* bg = (const float*)d_in[2];
    const float* Wv = (const float*)d_in[3];
    const float* bv = (const float*)d_in[4];
    const float* Wd = (const float*)d_in[5];
    const float* bd = (const float*)d_in[6];
    float* out = (float*)d_out;

    void *p_xh, *p_wh;
    cudaGetSymbolAddress(&p_xh, g_xh);
    cudaGetSymbolAddress(&p_wh, g_wh);

    static bool attr_set = false;
    if (!attr_set) {
        cudaFuncSetAttribute(gemm3_fp16_kernel,
                             cudaFuncAttributeMaxDynamicSharedMemorySize, GEMM_SMEM);
        attr_set = true;
    }

    convert_all_kernel<<<(NX4 + 3 * NW4) / 256, 256>>>(
        (const float4*)x, (const float4*)Wg, (const float4*)Wv, (const float4*)Wd,
        (uint2*)p_xh, (uint2*)p_wh);

    dim3 g1(Mdim / 128, Ddim / 64);      // (128, 16)
    gemm3_fp16_kernel<<<g1, 256, GEMM_SMEM>>>((const __half*)p_xh, (const __half*)p_wh,
                                              bg, bv, bd);

    carry_kernel<<<NCH / 256, 256>>>();                     // 16 blocks
    final_scan_kernel<<<(NCHUNK * NCH / 2) / 256, 256>>>(out);  // 512 blocks
}